// round 9
// baseline (speedup 1.0000x reference)
#include <cuda_runtime.h>
#include <cuda_fp16.h>
#include <mma.h>

using namespace nvcuda;

#define MAX_NODES 100000
#define MAX_EDGES 1600000
#define FDIM 128
#define SCAN_B 256
#define MAX_BLOCKS ((MAX_NODES + SCAN_B - 1) / SCAN_B)   // 391

// Scratch (allocation-free rule: __device__ globals)
__device__ int    g_deg[MAX_NODES];
__device__ float  g_dis[MAX_NODES];
__device__ int    g_rowptr[MAX_NODES + 1];
__device__ int    g_fill[MAX_NODES];
__device__ int    g_bsum[MAX_BLOCKS];
__device__ int    g_csr[MAX_EDGES];                   // src ids sorted by dst
__device__ __half g_xh[(size_t)MAX_NODES * FDIM];     // fp16 GEMM input (layer1: emb)
__device__ __half g_hb[(size_t)MAX_NODES * FDIM];     // fp16 dis-scaled GEMM output
__device__ __half g_ha[(size_t)MAX_NODES * FDIM];     // fp16 layer-1 aggregate out (GEMM2 in)
__device__ __half g_w1h[FDIM * FDIM];
__device__ __half g_w2h[FDIM * FDIM];

// ---------------- CSR build ----------------

__global__ void k_zero_deg(int n) {
    int i = blockIdx.x * blockDim.x + threadIdx.x;
    if (i < n) g_deg[i] = 0;
}

__global__ void k_count(const int* __restrict__ dst, int E) {
    int i = blockIdx.x * blockDim.x + threadIdx.x;
    if (i < E) atomicAdd(&g_deg[dst[i]], 1);
}

__global__ void k_dis(int n) {
    int i = blockIdx.x * blockDim.x + threadIdx.x;
    if (i < n) g_dis[i] = rsqrtf((float)(g_deg[i] + 1));  // +1 self-loop
}

__global__ void k_blocksum(int N) {
    __shared__ int s[SCAN_B];
    int i = blockIdx.x * SCAN_B + threadIdx.x;
    s[threadIdx.x] = (i < N) ? g_deg[i] : 0;
    __syncthreads();
#pragma unroll
    for (int off = SCAN_B / 2; off > 0; off >>= 1) {
        if (threadIdx.x < off) s[threadIdx.x] += s[threadIdx.x + off];
        __syncthreads();
    }
    if (threadIdx.x == 0) g_bsum[blockIdx.x] = s[0];
}

__global__ void k_scanbsums(int nb, int N) {
    __shared__ int s[1024];
    int t = threadIdx.x;
    int v = (t < nb) ? g_bsum[t] : 0;
    s[t] = v;
    __syncthreads();
    for (int off = 1; off < 1024; off <<= 1) {
        int u = (t >= off) ? s[t - off] : 0;
        __syncthreads();
        s[t] += u;
        __syncthreads();
    }
    if (t < nb) g_bsum[t] = s[t] - v;
    if (t == nb - 1) g_rowptr[N] = s[t];
}

__global__ void k_rowptr(int N) {
    __shared__ int s[SCAN_B];
    int i = blockIdx.x * SCAN_B + threadIdx.x;
    int t = threadIdx.x;
    int d = (i < N) ? g_deg[i] : 0;
    s[t] = d;
    __syncthreads();
#pragma unroll
    for (int off = 1; off < SCAN_B; off <<= 1) {
        int u = (t >= off) ? s[t - off] : 0;
        __syncthreads();
        s[t] += u;
        __syncthreads();
    }
    if (i < N) {
        int p = g_bsum[blockIdx.x] + s[t] - d;
        g_rowptr[i] = p;
        g_fill[i]   = p;
    }
}

__global__ void k_fill(const int* __restrict__ src, const int* __restrict__ dst, int E) {
    int i = blockIdx.x * blockDim.x + threadIdx.x;
    if (i < E) {
        int p = atomicAdd(&g_fill[dst[i]], 1);
        g_csr[p] = src[i];
    }
}

// ---------------- fp32 -> fp16 converts ----------------

__global__ void k_x2h(const float* __restrict__ X, __half* __restrict__ Xh, int n4) {
    int i = blockIdx.x * blockDim.x + threadIdx.x;   // over float4s
    if (i >= n4) return;
    float4 v = ((const float4*)X)[i];
    __half2 p0 = __floats2half2_rn(v.x, v.y);
    __half2 p1 = __floats2half2_rn(v.z, v.w);
    uint2 u; u.x = *(unsigned*)&p0; u.y = *(unsigned*)&p1;
    ((uint2*)Xh)[i] = u;
}

__global__ void k_w2h(const float* __restrict__ W1, const float* __restrict__ W2) {
    int i = blockIdx.x * blockDim.x + threadIdx.x;   // over FDIM*FDIM
    if (i < FDIM * FDIM) {
        g_w1h[i] = __float2half_rn(W1[i]);
        g_w2h[i] = __float2half_rn(W2[i]);
    }
}

// ---------------- Tensor-core GEMM: Hb[r,:] = fp16( dis[r] * (Xh[r,:] @ Wh) ) ----------------
// Block: 256 threads = 8 warps; tile 128 rows x 128 cols, K=128 in one pass.
// Dynamic smem: Xs (128x128 fp16, 32KB) + Ws (32KB) + Cs (8 warps x 256 fp32, 8KB) = 72KB.

__global__ __launch_bounds__(256) void k_gemm_tc(const __half* __restrict__ X,
                                                 const __half* __restrict__ Wh,
                                                 __half* __restrict__ H, int N)
{
    extern __shared__ char smraw[];
    __half* Xs = (__half*)smraw;                       // 128*128
    __half* Ws = Xs + 128 * 128;                       // 128*128
    float*  Cs = (float*)(Ws + 128 * 128);             // 8 * 256

    int t = threadIdx.x, wid = t >> 5, lane = t & 31;
    int row0 = blockIdx.x * 128;

    // Load W (16384 halfs = 2048 uint4)
    const uint4* W4 = (const uint4*)Wh;
    uint4* Ws4 = (uint4*)Ws;
#pragma unroll
    for (int i = 0; i < 8; i++) Ws4[t + i * 256] = W4[t + i * 256];

    // Load X tile (zero-pad past N)
    const uint4* X4 = (const uint4*)X;
    uint4* Xs4 = (uint4*)Xs;
#pragma unroll
    for (int i = 0; i < 8; i++) {
        int idx = t + i * 256;
        int r = idx >> 4, c = idx & 15;            // 16 uint4 per row
        uint4 v = make_uint4(0u, 0u, 0u, 0u);
        if (row0 + r < N) v = X4[(size_t)(row0 + r) * 16 + c];
        Xs4[idx] = v;
    }
    __syncthreads();

    // Preload 8 A fragments (this warp's 16 rows, all K)
    wmma::fragment<wmma::matrix_a, 16, 16, 16, __half, wmma::row_major> a[8];
#pragma unroll
    for (int k = 0; k < 8; k++)
        wmma::load_matrix_sync(a[k], Xs + wid * 16 * 128 + k * 16, 128);

    float* myC = Cs + wid * 256;
    int r = lane >> 1, cb = (lane & 1) * 8;        // epilogue mapping: 2 lanes per row
    int grow = row0 + wid * 16 + r;
    float s = (grow < N) ? g_dis[grow] : 0.f;

#pragma unroll
    for (int n = 0; n < 8; n++) {
        wmma::fragment<wmma::accumulator, 16, 16, 16, float> acc;
        wmma::fill_fragment(acc, 0.f);
#pragma unroll
        for (int k = 0; k < 8; k++) {
            wmma::fragment<wmma::matrix_b, 16, 16, 16, __half, wmma::row_major> b;
            wmma::load_matrix_sync(b, Ws + k * 16 * 128 + n * 16, 128);
            wmma::mma_sync(acc, a[k], b, acc);
        }
        wmma::store_matrix_sync(myC, acc, 16, wmma::mem_row_major);
        __syncwarp();
        if (grow < N) {
            const float* cp = myC + r * 16 + cb;
            __half2 h0 = __floats2half2_rn(cp[0] * s, cp[1] * s);
            __half2 h1 = __floats2half2_rn(cp[2] * s, cp[3] * s);
            __half2 h2 = __floats2half2_rn(cp[4] * s, cp[5] * s);
            __half2 h3 = __floats2half2_rn(cp[6] * s, cp[7] * s);
            uint4 u;
            u.x = *(unsigned*)&h0; u.y = *(unsigned*)&h1;
            u.z = *(unsigned*)&h2; u.w = *(unsigned*)&h3;
            *(uint4*)(H + (size_t)grow * FDIM + n * 16 + cb) = u;
        }
        __syncwarp();
    }
}

// ---------------- CSR aggregate + fused epilogue ----------------
// One warp per dst node; lane owns 4 features (8 B fp16 gather).
// Coalesced index preload (lane-parallel) + shfl distribution.
// out[v] = act( dis[v] * ( sum_{s in N(v)} hs[s] + hs[v] ) + b ),  hs = dis.*h

__global__ void k_aggregate(const __half* __restrict__ h, const float* __restrict__ bias,
                            float* __restrict__ outF, __half* __restrict__ outH,
                            int N, int doRelu)
{
    int lane = threadIdx.x & 31;
    int v = (blockIdx.x * blockDim.x + threadIdx.x) >> 5;
    if (v >= N) return;

    int b0 = g_rowptr[v];
    int deg = g_rowptr[v + 1] - b0;
    const uint2* h2 = (const uint2*)h;   // 32 uint2 per row

    float4 a0 = make_float4(0.f, 0.f, 0.f, 0.f);
    float4 a1 = a0, a2 = a0, a3 = a0;

    for (int base = 0; base < deg; base += 32) {
        int my = base + lane;
        int idx = (my < deg) ? g_csr[b0 + my] : 0;   // one coalesced load per 32 edges
        int cnt = deg - base; if (cnt > 32) cnt = 32;
        int j = 0;
        for (; j + 4 <= cnt; j += 4) {
            int s0 = __shfl_sync(0xffffffffu, idx, j);
            int s1 = __shfl_sync(0xffffffffu, idx, j + 1);
            int s2 = __shfl_sync(0xffffffffu, idx, j + 2);
            int s3 = __shfl_sync(0xffffffffu, idx, j + 3);
            uint2 u0 = h2[(size_t)s0 * 32 + lane];
            uint2 u1 = h2[(size_t)s1 * 32 + lane];
            uint2 u2 = h2[(size_t)s2 * 32 + lane];
            uint2 u3 = h2[(size_t)s3 * 32 + lane];
            float2 f;
            f = __half22float2(*(__half2*)&u0.x); a0.x += f.x; a0.y += f.y;
            f = __half22float2(*(__half2*)&u0.y); a0.z += f.x; a0.w += f.y;
            f = __half22float2(*(__half2*)&u1.x); a1.x += f.x; a1.y += f.y;
            f = __half22float2(*(__half2*)&u1.y); a1.z += f.x; a1.w += f.y;
            f = __half22float2(*(__half2*)&u2.x); a2.x += f.x; a2.y += f.y;
            f = __half22float2(*(__half2*)&u2.y); a2.z += f.x; a2.w += f.y;
            f = __half22float2(*(__half2*)&u3.x); a3.x += f.x; a3.y += f.y;
            f = __half22float2(*(__half2*)&u3.y); a3.z += f.x; a3.w += f.y;
        }
        for (; j < cnt; j++) {
            int s0 = __shfl_sync(0xffffffffu, idx, j);
            uint2 u0 = h2[(size_t)s0 * 32 + lane];
            float2 f;
            f = __half22float2(*(__half2*)&u0.x); a0.x += f.x; a0.y += f.y;
            f = __half22float2(*(__half2*)&u0.y); a0.z += f.x; a0.w += f.y;
        }
    }

    // self-loop term: + hs[v]
    {
        uint2 uv = h2[(size_t)v * 32 + lane];
        float2 f;
        f = __half22float2(*(__half2*)&uv.x); a1.x += f.x; a1.y += f.y;
        f = __half22float2(*(__half2*)&uv.y); a1.z += f.x; a1.w += f.y;
    }

    a0.x += a1.x + a2.x + a3.x;
    a0.y += a1.y + a2.y + a3.y;
    a0.z += a1.z + a2.z + a3.z;
    a0.w += a1.w + a2.w + a3.w;

    float dv = g_dis[v];
    float4 bv = ((const float4*)bias)[lane];

    float4 o;
    o.x = dv * a0.x + bv.x;
    o.y = dv * a0.y + bv.y;
    o.z = dv * a0.z + bv.z;
    o.w = dv * a0.w + bv.w;
    if (doRelu) {
        o.x = fmaxf(o.x, 0.f); o.y = fmaxf(o.y, 0.f);
        o.z = fmaxf(o.z, 0.f); o.w = fmaxf(o.w, 0.f);
    }
    if (outH) {
        __half2 p0 = __floats2half2_rn(o.x, o.y);
        __half2 p1 = __floats2half2_rn(o.z, o.w);
        uint2 u; u.x = *(unsigned*)&p0; u.y = *(unsigned*)&p1;
        ((uint2*)outH)[(size_t)v * 32 + lane] = u;
    } else {
        ((float4*)outF)[(size_t)v * 32 + lane] = o;
    }
}

// ---------------- launch ----------------

extern "C" void kernel_launch(void* const* d_in, const int* in_sizes, int n_in,
                              void* d_out, int out_size)
{
    const int*   eidx = (const int*)d_in[0];
    const float* emb  = (const float*)d_in[2];
    const float* W1   = (const float*)d_in[3];
    const float* b1   = (const float*)d_in[4];
    const float* W2   = (const float*)d_in[5];
    const float* b2   = (const float*)d_in[6];
    float* out = (float*)d_out;

    const int E = in_sizes[0] / 2;
    const int N = in_sizes[2] / FDIM;
    const int* src = eidx;
    const int* dst = eidx + E;

    const int GEMM_SMEM = (128 * 128 * 2) * 2 + 8 * 256 * 4;   // 65536 + 8192 = 73728 B
    cudaFuncSetAttribute(k_gemm_tc, cudaFuncAttributeMaxDynamicSharedMemorySize, GEMM_SMEM);

    __half* xh; cudaGetSymbolAddress((void**)&xh, g_xh);
    __half* hb; cudaGetSymbolAddress((void**)&hb, g_hb);
    __half* ha; cudaGetSymbolAddress((void**)&ha, g_ha);
    __half* w1h; cudaGetSymbolAddress((void**)&w1h, g_w1h);
    __half* w2h; cudaGetSymbolAddress((void**)&w2h, g_w2h);

    const int n4 = N * (FDIM / 4);
    const int nb = (N + 255) / 256;
    const int eb = (E + 255) / 256;
    const int scanBlocks = (N + SCAN_B - 1) / SCAN_B;
    const int gemmBlocks = (N + 127) / 128;
    const int aggBlocks = (N * 32 + 255) / 256;  // 1 warp/node

    // CSR build (by dst) + norms
    k_zero_deg<<<nb, 256>>>(N);
    k_count<<<eb, 256>>>(dst, E);
    k_dis<<<nb, 256>>>(N);
    k_blocksum<<<scanBlocks, SCAN_B>>>(N);
    k_scanbsums<<<1, 1024>>>(scanBlocks, N);
    k_rowptr<<<scanBlocks, SCAN_B>>>(N);
    k_fill<<<eb, 256>>>(src, dst, E);

    // fp16 converts
    k_x2h<<<(n4 + 255) / 256, 256>>>(emb, xh, n4);
    k_w2h<<<(FDIM * FDIM + 255) / 256, 256>>>(W1, W2);

    // ---- layer 1 ----
    k_gemm_tc<<<gemmBlocks, 256, GEMM_SMEM>>>(xh, w1h, hb, N);
    k_aggregate<<<aggBlocks, 256>>>(hb, b1, nullptr, ha, N, 1);

    // ---- layer 2 ----
    k_gemm_tc<<<gemmBlocks, 256, GEMM_SMEM>>>(ha, w2h, hb, N);
    k_aggregate<<<aggBlocks, 256>>>(hb, b2, out, nullptr, N, 0);
}